// round 1
// baseline (speedup 1.0000x reference)
#include <cuda_runtime.h>
#include <math_constants.h>

#define DIM    1024
#define NHEAD  16
#define HDIM   64
#define BATCH  4
#define SEQ    2048
#define MTOT   (BATCH * SEQ)      // 8192
#define ATTN_SCALE 0.125f         // 64^-0.5

// ---------------------------------------------------------------------------
// Scratch (no allocations allowed in kernel_launch): Q, K, V, attention-out,
// each [MTOT, DIM] fp32 in [B, N, H*d] layout (head h occupies cols h*64..h*64+63)
// ---------------------------------------------------------------------------
__device__ float g_Q [MTOT * DIM];
__device__ float g_K [MTOT * DIM];
__device__ float g_V [MTOT * DIM];
__device__ float g_AO[MTOT * DIM];

// ---------------------------------------------------------------------------
// SGEMM: C[M,1024] = A[M,1024] * W[1024,1024]^T   (C[m][n] = sum_k A[m][k]*W[n][k])
// 128x128 block tile, BK=16, 256 threads, 8x8 per-thread microkernel.
// ---------------------------------------------------------------------------
__global__ __launch_bounds__(256, 2)
void sgemm_xWT(const float* __restrict__ A,
               const float* __restrict__ W,
               float* __restrict__ C)
{
    __shared__ float As[16][132];   // [k][m], +4 pad keeps float4 alignment
    __shared__ float Ws[16][132];   // [k][n]

    const int tid = threadIdx.x;
    const int tx  = tid & 15;       // 0..15 -> n
    const int ty  = tid >> 4;       // 0..15 -> m
    const int m0  = blockIdx.y * 128;
    const int n0  = blockIdx.x * 128;

    float acc[8][8];
    #pragma unroll
    for (int i = 0; i < 8; ++i)
        #pragma unroll
        for (int j = 0; j < 8; ++j) acc[i][j] = 0.0f;

    for (int kt = 0; kt < DIM; kt += 16) {
        // Load 128x16 A tile and 128x16 W tile (each 512 float4, 2 per thread)
        #pragma unroll
        for (int p = 0; p < 2; ++p) {
            int slot = tid + p * 256;          // 0..511
            int row  = slot >> 2;              // 0..127
            int c4   = slot & 3;               // 0..3
            float4 va = *reinterpret_cast<const float4*>(
                &A[(size_t)(m0 + row) * DIM + kt + c4 * 4]);
            As[c4 * 4 + 0][row] = va.x;
            As[c4 * 4 + 1][row] = va.y;
            As[c4 * 4 + 2][row] = va.z;
            As[c4 * 4 + 3][row] = va.w;
            float4 vw = *reinterpret_cast<const float4*>(
                &W[(size_t)(n0 + row) * DIM + kt + c4 * 4]);
            Ws[c4 * 4 + 0][row] = vw.x;
            Ws[c4 * 4 + 1][row] = vw.y;
            Ws[c4 * 4 + 2][row] = vw.z;
            Ws[c4 * 4 + 3][row] = vw.w;
        }
        __syncthreads();

        #pragma unroll
        for (int k = 0; k < 16; ++k) {
            float a[8], b[8];
            #pragma unroll
            for (int i = 0; i < 8; i += 4) {
                float4 va = *reinterpret_cast<const float4*>(&As[k][ty * 8 + i]);
                a[i] = va.x; a[i+1] = va.y; a[i+2] = va.z; a[i+3] = va.w;
                float4 vb = *reinterpret_cast<const float4*>(&Ws[k][tx * 8 + i]);
                b[i] = vb.x; b[i+1] = vb.y; b[i+2] = vb.z; b[i+3] = vb.w;
            }
            #pragma unroll
            for (int i = 0; i < 8; ++i)
                #pragma unroll
                for (int j = 0; j < 8; ++j)
                    acc[i][j] = fmaf(a[i], b[j], acc[i][j]);
        }
        __syncthreads();
    }

    #pragma unroll
    for (int i = 0; i < 8; ++i) {
        float* crow = &C[(size_t)(m0 + ty * 8 + i) * DIM + n0 + tx * 8];
        #pragma unroll
        for (int j = 0; j < 8; j += 4) {
            float4 v = make_float4(acc[i][j], acc[i][j+1], acc[i][j+2], acc[i][j+3]);
            *reinterpret_cast<float4*>(crow + j) = v;
        }
    }
}

// ---------------------------------------------------------------------------
// Flash attention (fp32, causal). One block per (q-tile=64, head, batch).
// Q/K in smem as [d][row] (transposed), V as [k][c], P staged via smem.
// 256 threads, 4x4 register tile, width-16 shuffle row reductions.
// ---------------------------------------------------------------------------
#define SMP 65   // padded row stride

__global__ __launch_bounds__(256, 2)
void flash_attn(const float* __restrict__ Q,
                const float* __restrict__ K,
                const float* __restrict__ V,
                float* __restrict__ O)
{
    extern __shared__ float sm[];
    float* Qs = sm;                  // [64][SMP]  layout [d][q]
    float* Ks = sm + 1 * 64 * SMP;   // [64][SMP]  layout [d][k]
    float* Vs = sm + 2 * 64 * SMP;   // [64][SMP]  layout [k][c]
    float* Ps = sm + 3 * 64 * SMP;   // [64][SMP]  layout [k][q]

    const int tid = threadIdx.x;
    const int tn  = tid & 15;        // 0..15
    const int tm  = tid >> 4;        // 0..15
    const int qt  = blockIdx.x;      // 0..31
    const int h   = blockIdx.y;      // 0..15
    const int b   = blockIdx.z;      // 0..3
    const int q0  = qt * 64;
    const size_t base = (size_t)b * SEQ * DIM + (size_t)h * HDIM;

    // Load Q tile (64 rows x 64 d), store transposed [d][q]
    #pragma unroll
    for (int p = 0; p < 4; ++p) {
        int slot = tid + p * 256;    // 0..1023
        int row  = slot >> 4;        // 0..63
        int c4   = slot & 15;        // 0..15
        float4 v = *reinterpret_cast<const float4*>(
            &Q[base + (size_t)(q0 + row) * DIM + c4 * 4]);
        Qs[(c4 * 4 + 0) * SMP + row] = v.x;
        Qs[(c4 * 4 + 1) * SMP + row] = v.y;
        Qs[(c4 * 4 + 2) * SMP + row] = v.z;
        Qs[(c4 * 4 + 3) * SMP + row] = v.w;
    }

    float m_i[4], l_i[4], o[4][4];
    #pragma unroll
    for (int i = 0; i < 4; ++i) {
        m_i[i] = -CUDART_INF_F;
        l_i[i] = 0.0f;
        #pragma unroll
        for (int j = 0; j < 4; ++j) o[i][j] = 0.0f;
    }

    for (int kt = 0; kt <= qt; ++kt) {
        const int k0 = kt * 64;
        // Load K (transposed [d][k]) and V (natural [k][c]) tiles
        #pragma unroll
        for (int p = 0; p < 4; ++p) {
            int slot = tid + p * 256;
            int row  = slot >> 4;
            int c4   = slot & 15;
            float4 kv = *reinterpret_cast<const float4*>(
                &K[base + (size_t)(k0 + row) * DIM + c4 * 4]);
            Ks[(c4 * 4 + 0) * SMP + row] = kv.x;
            Ks[(c4 * 4 + 1) * SMP + row] = kv.y;
            Ks[(c4 * 4 + 2) * SMP + row] = kv.z;
            Ks[(c4 * 4 + 3) * SMP + row] = kv.w;
            float4 vv = *reinterpret_cast<const float4*>(
                &V[base + (size_t)(k0 + row) * DIM + c4 * 4]);
            Vs[row * SMP + c4 * 4 + 0] = vv.x;
            Vs[row * SMP + c4 * 4 + 1] = vv.y;
            Vs[row * SMP + c4 * 4 + 2] = vv.z;
            Vs[row * SMP + c4 * 4 + 3] = vv.w;
        }
        __syncthreads();

        // S = Q * K^T (4x4 per thread over d=64)
        float s[4][4];
        #pragma unroll
        for (int i = 0; i < 4; ++i)
            #pragma unroll
            for (int j = 0; j < 4; ++j) s[i][j] = 0.0f;

        #pragma unroll 8
        for (int dd = 0; dd < 64; ++dd) {
            float qv[4], kv[4];
            #pragma unroll
            for (int i = 0; i < 4; ++i) qv[i] = Qs[dd * SMP + tm * 4 + i];
            #pragma unroll
            for (int j = 0; j < 4; ++j) kv[j] = Ks[dd * SMP + tn * 4 + j];
            #pragma unroll
            for (int i = 0; i < 4; ++i)
                #pragma unroll
                for (int j = 0; j < 4; ++j)
                    s[i][j] = fmaf(qv[i], kv[j], s[i][j]);
        }

        // scale + causal mask (only diagonal tile needs masking)
        if (kt == qt) {
            #pragma unroll
            for (int i = 0; i < 4; ++i)
                #pragma unroll
                for (int j = 0; j < 4; ++j)
                    s[i][j] = (tm * 4 + i >= tn * 4 + j)
                            ? s[i][j] * ATTN_SCALE : -CUDART_INF_F;
        } else {
            #pragma unroll
            for (int i = 0; i < 4; ++i)
                #pragma unroll
                for (int j = 0; j < 4; ++j)
                    s[i][j] *= ATTN_SCALE;
        }

        // Online softmax per row (16 lanes per row, width-16 shuffles)
        #pragma unroll
        for (int i = 0; i < 4; ++i) {
            float mx = fmaxf(fmaxf(s[i][0], s[i][1]), fmaxf(s[i][2], s[i][3]));
            #pragma unroll
            for (int off = 8; off > 0; off >>= 1)
                mx = fmaxf(mx, __shfl_xor_sync(0xffffffffu, mx, off, 16));
            float mnew  = fmaxf(m_i[i], mx);
            float alpha = __expf(m_i[i] - mnew);
            float rs = 0.0f;
            #pragma unroll
            for (int j = 0; j < 4; ++j) {
                float pe = __expf(s[i][j] - mnew);
                s[i][j] = pe;
                rs += pe;
            }
            #pragma unroll
            for (int off = 8; off > 0; off >>= 1)
                rs += __shfl_xor_sync(0xffffffffu, rs, off, 16);
            l_i[i] = l_i[i] * alpha + rs;
            m_i[i] = mnew;
            #pragma unroll
            for (int j = 0; j < 4; ++j) o[i][j] *= alpha;
        }

        // Stage P to smem as [k][q]
        #pragma unroll
        for (int i = 0; i < 4; ++i)
            #pragma unroll
            for (int j = 0; j < 4; ++j)
                Ps[(tn * 4 + j) * SMP + tm * 4 + i] = s[i][j];
        __syncthreads();

        // O += P * V (4x4 per thread over k=64)
        #pragma unroll 8
        for (int kk = 0; kk < 64; ++kk) {
            float pv[4], vv[4];
            #pragma unroll
            for (int i = 0; i < 4; ++i) pv[i] = Ps[kk * SMP + tm * 4 + i];
            #pragma unroll
            for (int j = 0; j < 4; ++j) vv[j] = Vs[kk * SMP + tn * 4 + j];
            #pragma unroll
            for (int i = 0; i < 4; ++i)
                #pragma unroll
                for (int j = 0; j < 4; ++j)
                    o[i][j] = fmaf(pv[i], vv[j], o[i][j]);
        }
        __syncthreads();
    }

    // Normalize and write out (same [B,N,H*d] layout as Q)
    #pragma unroll
    for (int i = 0; i < 4; ++i) {
        float inv_l = 1.0f / l_i[i];
        #pragma unroll
        for (int j = 0; j < 4; ++j)
            O[base + (size_t)(q0 + tm * 4 + i) * DIM + tn * 4 + j] = o[i][j] * inv_l;
    }
}

// ---------------------------------------------------------------------------
// Launch: QKV projections -> flash attention -> output projection
// Inputs (metadata order): x, mask(bool, unused - causality computed directly),
//                          Wq, Wk, Wv, Wo
// ---------------------------------------------------------------------------
extern "C" void kernel_launch(void* const* d_in, const int* in_sizes, int n_in,
                              void* d_out, int out_size)
{
    const float* x  = (const float*)d_in[0];
    const float* Wq = (const float*)d_in[2];
    const float* Wk = (const float*)d_in[3];
    const float* Wv = (const float*)d_in[4];
    const float* Wo = (const float*)d_in[5];
    float* out = (float*)d_out;

    float *Qd, *Kd, *Vd, *AOd;
    cudaGetSymbolAddress((void**)&Qd,  g_Q);
    cudaGetSymbolAddress((void**)&Kd,  g_K);
    cudaGetSymbolAddress((void**)&Vd,  g_V);
    cudaGetSymbolAddress((void**)&AOd, g_AO);

    const int smem_flash = 4 * 64 * SMP * sizeof(float);   // 66560 B
    cudaFuncSetAttribute(flash_attn,
                         cudaFuncAttributeMaxDynamicSharedMemorySize, smem_flash);

    dim3 gGemm(DIM / 128, MTOT / 128);   // (8, 64)
    dim3 bGemm(256);

    sgemm_xWT<<<gGemm, bGemm>>>(x, Wq, Qd);
    sgemm_xWT<<<gGemm, bGemm>>>(x, Wk, Kd);
    sgemm_xWT<<<gGemm, bGemm>>>(x, Wv, Vd);

    dim3 gFlash(SEQ / 64, NHEAD, BATCH); // (32, 16, 4)
    flash_attn<<<gFlash, 256, smem_flash>>>(Qd, Kd, Vd, AOd);

    sgemm_xWT<<<gGemm, bGemm>>>(AOd, Wo, out);
}

// round 2
// speedup vs baseline: 2.8058x; 2.8058x over previous
#include <cuda_runtime.h>
#include <math_constants.h>
#include <cstdint>

#define DIM    1024
#define NHEAD  16
#define HDIM   64
#define BATCH  4
#define SEQ    2048
#define MTOT   (BATCH * SEQ)      // 8192
#define ATTN_SCALE 0.125f         // 64^-0.5

// ---------------------------------------------------------------------------
// Scratch: Q, K, V, attention-out, each [MTOT, DIM] fp32 in [B, N, H*d] layout
// ---------------------------------------------------------------------------
__device__ float g_Q [MTOT * DIM];
__device__ float g_K [MTOT * DIM];
__device__ float g_V [MTOT * DIM];
__device__ float g_AO[MTOT * DIM];

// ---------------------------------------------------------------------------
// tf32 helpers
// ---------------------------------------------------------------------------
__device__ __forceinline__ unsigned f2tf(float x) {
    unsigned u;
    asm("cvt.rna.tf32.f32 %0, %1;" : "=r"(u) : "f"(x));
    return u;
}

__device__ __forceinline__ void mma_tf32(float* c,
                                         unsigned a0, unsigned a1,
                                         unsigned a2, unsigned a3,
                                         unsigned b0, unsigned b1) {
    asm volatile(
        "mma.sync.aligned.m16n8k8.row.col.f32.tf32.tf32.f32 "
        "{%0,%1,%2,%3},{%4,%5,%6,%7},{%8,%9},{%0,%1,%2,%3};\n"
        : "+f"(c[0]), "+f"(c[1]), "+f"(c[2]), "+f"(c[3])
        : "r"(a0), "r"(a1), "r"(a2), "r"(a3), "r"(b0), "r"(b1));
}

// ---------------------------------------------------------------------------
// TF32 GEMM: C[M,1024] = A[M,1024] * W[1024,1024]^T
// 128x128 block tile, BK=16, 256 threads / 8 warps, warp tile 32x64.
// Smem layout [row][k] with stride 20 words (conflict-free fragment loads).
// ---------------------------------------------------------------------------
#define GST 20

__global__ __launch_bounds__(256, 2)
void gemm_tf32(const float* __restrict__ A,
               const float* __restrict__ W,
               float* __restrict__ C)
{
    __shared__ unsigned As[128 * GST];   // A tile [m][k]
    __shared__ unsigned Bs[128 * GST];   // W tile [n][k]

    const int tid  = threadIdx.x;
    const int lane = tid & 31;
    const int warp = tid >> 5;
    const int wm   = warp & 3;          // 0..3 -> m offset wm*32
    const int wn   = warp >> 2;         // 0..1 -> n offset wn*64
    const int r    = lane >> 2;         // groupID 0..7
    const int t    = lane & 3;          // threadID-in-group 0..3
    const int m0   = blockIdx.y * 128;
    const int n0   = blockIdx.x * 128;

    float c[2][8][4];
    #pragma unroll
    for (int mi = 0; mi < 2; ++mi)
        #pragma unroll
        for (int ni = 0; ni < 8; ++ni)
            #pragma unroll
            for (int j = 0; j < 4; ++j) c[mi][ni][j] = 0.0f;

    for (int kt = 0; kt < DIM; kt += 16) {
        // Load 128x16 A and W tiles (512 float4 each, 2 per thread each)
        #pragma unroll
        for (int p = 0; p < 2; ++p) {
            int slot = tid + p * 256;           // 0..511
            int row  = slot >> 2;               // 0..127
            int c4   = (slot & 3) * 4;          // 0,4,8,12
            float4 va = *reinterpret_cast<const float4*>(
                &A[(size_t)(m0 + row) * DIM + kt + c4]);
            unsigned* da = &As[row * GST + c4];
            da[0] = f2tf(va.x); da[1] = f2tf(va.y);
            da[2] = f2tf(va.z); da[3] = f2tf(va.w);
            float4 vw = *reinterpret_cast<const float4*>(
                &W[(size_t)(n0 + row) * DIM + kt + c4]);
            unsigned* db = &Bs[row * GST + c4];
            db[0] = f2tf(vw.x); db[1] = f2tf(vw.y);
            db[2] = f2tf(vw.z); db[3] = f2tf(vw.w);
        }
        __syncthreads();

        #pragma unroll
        for (int ks = 0; ks < 16; ks += 8) {
            unsigned a[2][4];
            #pragma unroll
            for (int mi = 0; mi < 2; ++mi) {
                const unsigned* ab = &As[(wm * 32 + mi * 16) * GST + ks + t];
                a[mi][0] = ab[r * GST];
                a[mi][1] = ab[(r + 8) * GST];
                a[mi][2] = ab[r * GST + 4];
                a[mi][3] = ab[(r + 8) * GST + 4];
            }
            #pragma unroll
            for (int ni = 0; ni < 8; ++ni) {
                const unsigned* bb = &Bs[(wn * 64 + ni * 8 + r) * GST + ks + t];
                unsigned b0 = bb[0], b1 = bb[4];
                mma_tf32(c[0][ni], a[0][0], a[0][1], a[0][2], a[0][3], b0, b1);
                mma_tf32(c[1][ni], a[1][0], a[1][1], a[1][2], a[1][3], b0, b1);
            }
        }
        __syncthreads();
    }

    #pragma unroll
    for (int mi = 0; mi < 2; ++mi) {
        #pragma unroll
        for (int ni = 0; ni < 8; ++ni) {
            int row = m0 + wm * 32 + mi * 16 + r;
            int col = n0 + wn * 64 + ni * 8 + 2 * t;
            float2 v01 = make_float2(c[mi][ni][0], c[mi][ni][1]);
            float2 v23 = make_float2(c[mi][ni][2], c[mi][ni][3]);
            *reinterpret_cast<float2*>(&C[(size_t)row * DIM + col])       = v01;
            *reinterpret_cast<float2*>(&C[(size_t)(row + 8) * DIM + col]) = v23;
        }
    }
}

// ---------------------------------------------------------------------------
// Flash attention, tf32 tensor cores. One block per (q-tile=64, head, batch).
// 128 threads / 4 warps; warp w owns q-rows w*16..w*16+15 -> softmax reduces
// entirely within width-4 shuffles. P round-trips through smem (A-frag layout).
// Strides: Qs/Ks/Ps = 68 (A-pattern conflict-free), Vs = 72 (B-pattern).
// ---------------------------------------------------------------------------
#define QST 68
#define VST 72

__global__ __launch_bounds__(128)
void flash_tf32(const float* __restrict__ Q,
                const float* __restrict__ K,
                const float* __restrict__ V,
                float* __restrict__ O)
{
    extern __shared__ unsigned sm[];
    unsigned* Qs = sm;                    // [64][QST]  q rows x d
    unsigned* Ks = sm + 64 * QST;         // [64][QST]  k rows x d
    unsigned* Ps = sm + 2 * 64 * QST;     // [64][QST]  q rows x k
    unsigned* Vs = sm + 3 * 64 * QST;     // [64][VST]  k rows x d

    const int tid  = threadIdx.x;
    const int lane = tid & 31;
    const int warp = tid >> 5;            // 0..3
    const int r    = lane >> 2;           // 0..7
    const int t    = lane & 3;            // 0..3
    const int qt   = blockIdx.x;          // 0..31
    const int h    = blockIdx.y;
    const int b    = blockIdx.z;
    const int q0   = qt * 64;
    const size_t base = (size_t)b * SEQ * DIM + (size_t)h * HDIM;

    // Load Q tile (64 x 64), cvt to tf32
    #pragma unroll
    for (int p = 0; p < 8; ++p) {
        int slot = tid + p * 128;          // 0..1023
        int row  = slot >> 4;              // 0..63
        int c4   = (slot & 15) * 4;        // 0..60
        float4 v = *reinterpret_cast<const float4*>(
            &Q[base + (size_t)(q0 + row) * DIM + c4]);
        unsigned* d = &Qs[row * QST + c4];
        d[0] = f2tf(v.x); d[1] = f2tf(v.y); d[2] = f2tf(v.z); d[3] = f2tf(v.w);
    }

    float m_i[2] = {-CUDART_INF_F, -CUDART_INF_F};
    float l_i[2] = {0.0f, 0.0f};
    float o[8][4];
    #pragma unroll
    for (int ni = 0; ni < 8; ++ni)
        #pragma unroll
        for (int j = 0; j < 4; ++j) o[ni][j] = 0.0f;

    const int row_loc = warp * 16 + r;    // local q row (lower half; +8 upper)

    for (int kt = 0; kt <= qt; ++kt) {
        const int k0 = kt * 64;
        // Load K and V tiles
        #pragma unroll
        for (int p = 0; p < 8; ++p) {
            int slot = tid + p * 128;
            int row  = slot >> 4;
            int c4   = (slot & 15) * 4;
            float4 kv = *reinterpret_cast<const float4*>(
                &K[base + (size_t)(k0 + row) * DIM + c4]);
            unsigned* dk = &Ks[row * QST + c4];
            dk[0] = f2tf(kv.x); dk[1] = f2tf(kv.y);
            dk[2] = f2tf(kv.z); dk[3] = f2tf(kv.w);
            float4 vv = *reinterpret_cast<const float4*>(
                &V[base + (size_t)(k0 + row) * DIM + c4]);
            unsigned* dv = &Vs[row * VST + c4];
            dv[0] = f2tf(vv.x); dv[1] = f2tf(vv.y);
            dv[2] = f2tf(vv.z); dv[3] = f2tf(vv.w);
        }
        __syncthreads();

        // ---- S = Q K^T : warp computes 16 x 64 ----
        float s[8][4];
        #pragma unroll
        for (int ni = 0; ni < 8; ++ni)
            #pragma unroll
            for (int j = 0; j < 4; ++j) s[ni][j] = 0.0f;

        #pragma unroll
        for (int ks = 0; ks < 8; ++ks) {
            const unsigned* ab = &Qs[(warp * 16) * QST + ks * 8 + t];
            unsigned a0 = ab[r * QST];
            unsigned a1 = ab[(r + 8) * QST];
            unsigned a2 = ab[r * QST + 4];
            unsigned a3 = ab[(r + 8) * QST + 4];
            #pragma unroll
            for (int ni = 0; ni < 8; ++ni) {
                const unsigned* bb = &Ks[(ni * 8 + r) * QST + ks * 8 + t];
                mma_tf32(s[ni], a0, a1, a2, a3, bb[0], bb[4]);
            }
        }

        // ---- scale + causal mask ----
        if (kt == qt) {
            #pragma unroll
            for (int ni = 0; ni < 8; ++ni) {
                int col = ni * 8 + 2 * t;
                s[ni][0] = (col     <= row_loc    ) ? s[ni][0] * ATTN_SCALE : -CUDART_INF_F;
                s[ni][1] = (col + 1 <= row_loc    ) ? s[ni][1] * ATTN_SCALE : -CUDART_INF_F;
                s[ni][2] = (col     <= row_loc + 8) ? s[ni][2] * ATTN_SCALE : -CUDART_INF_F;
                s[ni][3] = (col + 1 <= row_loc + 8) ? s[ni][3] * ATTN_SCALE : -CUDART_INF_F;
            }
        } else {
            #pragma unroll
            for (int ni = 0; ni < 8; ++ni)
                #pragma unroll
                for (int j = 0; j < 4; ++j) s[ni][j] *= ATTN_SCALE;
        }

        // ---- online softmax (rows r and r+8), width-4 shuffles ----
        #pragma unroll
        for (int hh = 0; hh < 2; ++hh) {
            float mx = -CUDART_INF_F;
            #pragma unroll
            for (int ni = 0; ni < 8; ++ni)
                mx = fmaxf(mx, fmaxf(s[ni][hh * 2], s[ni][hh * 2 + 1]));
            mx = fmaxf(mx, __shfl_xor_sync(0xffffffffu, mx, 1, 4));
            mx = fmaxf(mx, __shfl_xor_sync(0xffffffffu, mx, 2, 4));
            float mnew  = fmaxf(m_i[hh], mx);
            float alpha = __expf(m_i[hh] - mnew);
            m_i[hh] = mnew;
            float rs = 0.0f;
            #pragma unroll
            for (int ni = 0; ni < 8; ++ni) {
                float p0 = __expf(s[ni][hh * 2]     - mnew);
                float p1 = __expf(s[ni][hh * 2 + 1] - mnew);
                s[ni][hh * 2]     = p0;
                s[ni][hh * 2 + 1] = p1;
                rs += p0 + p1;
            }
            rs += __shfl_xor_sync(0xffffffffu, rs, 1, 4);
            rs += __shfl_xor_sync(0xffffffffu, rs, 2, 4);
            l_i[hh] = l_i[hh] * alpha + rs;
            #pragma unroll
            for (int ni = 0; ni < 8; ++ni) {
                o[ni][hh * 2]     *= alpha;
                o[ni][hh * 2 + 1] *= alpha;
            }
        }

        // ---- stage P to smem in A-frag layout (own warp's rows only) ----
        #pragma unroll
        for (int ni = 0; ni < 8; ++ni) {
            uint2 p01 = make_uint2(f2tf(s[ni][0]), f2tf(s[ni][1]));
            uint2 p23 = make_uint2(f2tf(s[ni][2]), f2tf(s[ni][3]));
            *reinterpret_cast<uint2*>(&Ps[row_loc * QST + ni * 8 + 2 * t])       = p01;
            *reinterpret_cast<uint2*>(&Ps[(row_loc + 8) * QST + ni * 8 + 2 * t]) = p23;
        }
        __syncwarp();

        // ---- O += P V : warp computes 16 x 64 ----
        #pragma unroll
        for (int ks = 0; ks < 8; ++ks) {
            const unsigned* ab = &Ps[(warp * 16) * QST + ks * 8 + t];
            unsigned a0 = ab[r * QST];
            unsigned a1 = ab[(r + 8) * QST];
            unsigned a2 = ab[r * QST + 4];
            unsigned a3 = ab[(r + 8) * QST + 4];
            #pragma unroll
            for (int ni = 0; ni < 8; ++ni) {
                unsigned b0 = Vs[(ks * 8 + t) * VST + ni * 8 + r];
                unsigned b1 = Vs[(ks * 8 + t + 4) * VST + ni * 8 + r];
                mma_tf32(o[ni], a0, a1, a2, a3, b0, b1);
            }
        }
        __syncthreads();
    }

    // ---- normalize + write out ----
    #pragma unroll
    for (int hh = 0; hh < 2; ++hh) {
        float inv_l = 1.0f / l_i[hh];
        int row = q0 + row_loc + hh * 8;
        #pragma unroll
        for (int ni = 0; ni < 8; ++ni) {
            float2 v = make_float2(o[ni][hh * 2] * inv_l, o[ni][hh * 2 + 1] * inv_l);
            *reinterpret_cast<float2*>(
                &O[base + (size_t)row * DIM + ni * 8 + 2 * t]) = v;
        }
    }
}

// ---------------------------------------------------------------------------
// Launch: QKV projections -> flash attention -> output projection
// Inputs (metadata order): x, mask(unused), Wq, Wk, Wv, Wo
// ---------------------------------------------------------------------------
extern "C" void kernel_launch(void* const* d_in, const int* in_sizes, int n_in,
                              void* d_out, int out_size)
{
    const float* x  = (const float*)d_in[0];
    const float* Wq = (const float*)d_in[2];
    const float* Wk = (const float*)d_in[3];
    const float* Wv = (const float*)d_in[4];
    const float* Wo = (const float*)d_in[5];
    float* out = (float*)d_out;

    float *Qd, *Kd, *Vd, *AOd;
    cudaGetSymbolAddress((void**)&Qd,  g_Q);
    cudaGetSymbolAddress((void**)&Kd,  g_K);
    cudaGetSymbolAddress((void**)&Vd,  g_V);
    cudaGetSymbolAddress((void**)&AOd, g_AO);

    const int smem_flash = (3 * 64 * QST + 64 * VST) * sizeof(unsigned); // 70656 B
    static bool attr_set = false;
    if (!attr_set) {
        cudaFuncSetAttribute(flash_tf32,
                             cudaFuncAttributeMaxDynamicSharedMemorySize, smem_flash);
        attr_set = true;
    }

    dim3 gGemm(DIM / 128, MTOT / 128);   // (8, 64)
    dim3 bGemm(256);

    gemm_tf32<<<gGemm, bGemm>>>(x, Wq, Qd);
    gemm_tf32<<<gGemm, bGemm>>>(x, Wk, Kd);
    gemm_tf32<<<gGemm, bGemm>>>(x, Wv, Vd);

    dim3 gFlash(SEQ / 64, NHEAD, BATCH); // (32, 16, 4)
    flash_tf32<<<gFlash, 128, smem_flash>>>(Qd, Kd, Vd, AOd);

    gemm_tf32<<<gGemm, bGemm>>>(AOd, Wo, out);
}

// round 4
// speedup vs baseline: 3.5068x; 1.2498x over previous
#include <cuda_runtime.h>
#include <math_constants.h>
#include <cstdint>

#define DIM    1024
#define NHEAD  16
#define HDIM   64
#define BATCH  4
#define SEQ    2048
#define MTOT   (BATCH * SEQ)      // 8192
#define ATTN_SCALE 0.125f

// ---------------------------------------------------------------------------
// Scratch
// ---------------------------------------------------------------------------
__device__ float g_QKV[3 * MTOT * DIM];   // Q,K,V (tf32-rounded)
__device__ float g_AO [MTOT * DIM];       // attention out (tf32-rounded)
__device__ float g_Xt [MTOT * DIM];       // tf32-rounded x
__device__ float g_Wt [4 * DIM * DIM];    // tf32-rounded Wq,Wk,Wv,Wo

// ---------------------------------------------------------------------------
// Helpers
// ---------------------------------------------------------------------------
__device__ __forceinline__ unsigned f2tf(float x) {
    unsigned u;
    asm("cvt.rna.tf32.f32 %0, %1;" : "=r"(u) : "f"(x));
    return u;
}

__device__ __forceinline__ uint32_t smem_u32(const void* p) {
    uint32_t a;
    asm("{ .reg .u64 t; cvta.to.shared.u64 t, %1; cvt.u32.u64 %0, t; }"
        : "=r"(a) : "l"(p));
    return a;
}

__device__ __forceinline__ void mma_tf32(float* c,
                                         unsigned a0, unsigned a1,
                                         unsigned a2, unsigned a3,
                                         unsigned b0, unsigned b1) {
    asm volatile(
        "mma.sync.aligned.m16n8k8.row.col.f32.tf32.tf32.f32 "
        "{%0,%1,%2,%3},{%4,%5,%6,%7},{%8,%9},{%0,%1,%2,%3};\n"
        : "+f"(c[0]), "+f"(c[1]), "+f"(c[2]), "+f"(c[3])
        : "r"(a0), "r"(a1), "r"(a2), "r"(a3), "r"(b0), "r"(b1));
}

#define CP_ASYNC16(dst, src) \
    asm volatile("cp.async.cg.shared.global [%0], [%1], 16;" \
                 :: "r"(dst), "l"(src) : "memory")
#define CP_COMMIT() asm volatile("cp.async.commit_group;" ::: "memory")
#define CP_WAIT(N)  asm volatile("cp.async.wait_group %0;" :: "n"(N) : "memory")

// ---------------------------------------------------------------------------
// Pre-pass: fp32 -> tf32-rounded fp32
// ---------------------------------------------------------------------------
__global__ void cvt_tf32_k(const float4* __restrict__ src,
                           float4* __restrict__ dst, int n4)
{
    int i = blockIdx.x * blockDim.x + threadIdx.x;
    int stride = gridDim.x * blockDim.x;
    for (; i < n4; i += stride) {
        float4 v = src[i];
        v.x = __uint_as_float(f2tf(v.x));
        v.y = __uint_as_float(f2tf(v.y));
        v.z = __uint_as_float(f2tf(v.z));
        v.w = __uint_as_float(f2tf(v.w));
        dst[i] = v;
    }
}

// ---------------------------------------------------------------------------
// TF32 GEMM, warp mma.sync, 3-stage cp.async pipeline.
// C[M,1024] = A * W^T. Tile 128x128, BK=32, 256 thr / 8 warps, warp 32x64.
// A,W must already be tf32-rounded. grid.z selects W / C slab (fused QKV).
// ---------------------------------------------------------------------------
#define GST     36                    // smem row stride (words)
#define BK      32
#define NCH     (DIM / BK)            // 32
#define AWORDS  (128 * GST)           // 4608 words
#define STGW    (2 * AWORDS)          // 9216 words per stage
#define STGB    (STGW * 4)            // 36864 B
#define SMEM_GEMM (3 * STGB)          // 110592 B

template<bool ROUND>
__global__ __launch_bounds__(256)
void gemm_tc(const float* __restrict__ Abase,
             const float* __restrict__ Wbase,
             float* __restrict__ Cbase)
{
    extern __shared__ float smf[];
    const uint32_t sbase = smem_u32(smf);

    const int tid  = threadIdx.x;
    const int lane = tid & 31;
    const int warp = tid >> 5;
    const int wm   = warp & 3;
    const int wn   = warp >> 2;
    const int r    = lane >> 2;
    const int t    = lane & 3;
    const int m0   = blockIdx.y * 128;
    const int n0   = blockIdx.x * 128;

    const float* A = Abase;
    const float* W = Wbase + (size_t)blockIdx.z * DIM * DIM;
    float*       C = Cbase + (size_t)blockIdx.z * MTOT * DIM;

    float c[2][8][4];
    #pragma unroll
    for (int mi = 0; mi < 2; ++mi)
        #pragma unroll
        for (int ni = 0; ni < 8; ++ni)
            #pragma unroll
            for (int j = 0; j < 4; ++j) c[mi][ni][j] = 0.0f;

    // per-thread load slots: 4 float4 for A, 4 for W per stage
    int lrow[4], lc4[4];
    #pragma unroll
    for (int p = 0; p < 4; ++p) {
        int slot = tid + p * 256;      // 0..1023
        lrow[p] = slot >> 3;           // 0..127
        lc4[p]  = (slot & 7) * 4;      // 0..28
    }

    auto load_stage = [&](int ch, int s) {
        const float* Ab = A + (size_t)m0 * DIM + ch * BK;
        const float* Wb = W + (size_t)n0 * DIM + ch * BK;
        const uint32_t as = sbase + s * STGB;
        const uint32_t bs = as + AWORDS * 4;
        #pragma unroll
        for (int p = 0; p < 4; ++p) {
            uint32_t off = (lrow[p] * GST + lc4[p]) * 4;
            CP_ASYNC16(as + off, Ab + (size_t)lrow[p] * DIM + lc4[p]);
            CP_ASYNC16(bs + off, Wb + (size_t)lrow[p] * DIM + lc4[p]);
        }
        CP_COMMIT();
    };

    load_stage(0, 0);
    load_stage(1, 1);

    for (int ch = 0; ch < NCH; ++ch) {
        if (ch < NCH - 1) { CP_WAIT(1); } else { CP_WAIT(0); }
        __syncthreads();
        if (ch + 2 < NCH) load_stage(ch + 2, (ch + 2) % 3);

        const unsigned* As = reinterpret_cast<const unsigned*>(smf) + (ch % 3) * STGW;
        const unsigned* Bs = As + AWORDS;

        #pragma unroll
        for (int ks = 0; ks < 4; ++ks) {
            unsigned a[2][4];
            #pragma unroll
            for (int mi = 0; mi < 2; ++mi) {
                const unsigned* ab = &As[(wm * 32 + mi * 16) * GST + ks * 8 + t];
                a[mi][0] = ab[r * GST];
                a[mi][1] = ab[(r + 8) * GST];
                a[mi][2] = ab[r * GST + 4];
                a[mi][3] = ab[(r + 8) * GST + 4];
            }
            #pragma unroll
            for (int ni = 0; ni < 8; ++ni) {
                const unsigned* bb = &Bs[(wn * 64 + ni * 8 + r) * GST + ks * 8 + t];
                unsigned b0 = bb[0], b1 = bb[4];
                mma_tf32(c[0][ni], a[0][0], a[0][1], a[0][2], a[0][3], b0, b1);
                mma_tf32(c[1][ni], a[1][0], a[1][1], a[1][2], a[1][3], b0, b1);
            }
        }
    }

    #pragma unroll
    for (int mi = 0; mi < 2; ++mi) {
        #pragma unroll
        for (int ni = 0; ni < 8; ++ni) {
            int row = m0 + wm * 32 + mi * 16 + r;
            int col = n0 + wn * 64 + ni * 8 + 2 * t;
            float v0 = c[mi][ni][0], v1 = c[mi][ni][1];
            float v2 = c[mi][ni][2], v3 = c[mi][ni][3];
            if (ROUND) {
                v0 = __uint_as_float(f2tf(v0)); v1 = __uint_as_float(f2tf(v1));
                v2 = __uint_as_float(f2tf(v2)); v3 = __uint_as_float(f2tf(v3));
            }
            *reinterpret_cast<float2*>(&C[(size_t)row * DIM + col])       = make_float2(v0, v1);
            *reinterpret_cast<float2*>(&C[(size_t)(row + 8) * DIM + col]) = make_float2(v2, v3);
        }
    }
}

// ---------------------------------------------------------------------------
// Flash attention. Q-tile 128 (8 warps / 256 thr), K-tile 64.
// Q/K/V already tf32-rounded -> raw bit loads, no cvt in hot loop.
// Warp w owns q-rows w*16..w*16+15; softmax via width-4 shuffles.
// ---------------------------------------------------------------------------
#define QST 68
#define VST 72
#define FL_SMEMW (128 * QST + 64 * QST + 128 * QST + 64 * VST)   // 26368 words

__global__ __launch_bounds__(256)
void flash_tf32(const float* __restrict__ Q,
                const float* __restrict__ K,
                const float* __restrict__ V,
                float* __restrict__ O)
{
    extern __shared__ unsigned sm[];
    unsigned* Qs = sm;                          // [128][QST]
    unsigned* Ks = sm + 128 * QST;              // [64][QST]
    unsigned* Ps = sm + 128 * QST + 64 * QST;   // [128][QST]
    unsigned* Vs = sm + 256 * QST + 64 * QST;   // [64][VST]

    const int tid  = threadIdx.x;
    const int lane = tid & 31;
    const int warp = tid >> 5;           // 0..7
    const int r    = lane >> 2;
    const int t    = lane & 3;
    const int h    = blockIdx.y;
    const int b    = blockIdx.z;
    const int q0   = blockIdx.x * 128;
    const size_t base = (size_t)b * SEQ * DIM + (size_t)h * HDIM;

    // Q tile: 128 rows x 16 uint4 = 2048 slots (8/thread), raw bits
    #pragma unroll
    for (int p = 0; p < 8; ++p) {
        int slot = tid + p * 256;
        int row  = slot >> 4;
        int c4   = (slot & 15) * 4;
        uint4 v = *reinterpret_cast<const uint4*>(
            &Q[base + (size_t)(q0 + row) * DIM + c4]);
        *reinterpret_cast<uint4*>(&Qs[row * QST + c4]) = v;
    }

    float m_i[2] = {-CUDART_INF_F, -CUDART_INF_F};
    float l_i[2] = {0.0f, 0.0f};
    float o[8][4];
    #pragma unroll
    for (int ni = 0; ni < 8; ++ni)
        #pragma unroll
        for (int j = 0; j < 4; ++j) o[ni][j] = 0.0f;

    const int row_loc = warp * 16 + r;
    const int ktmax   = 2 * blockIdx.x + 1;

    for (int kt = 0; kt <= ktmax; ++kt) {
        const int k0 = kt * 64;
        // K,V tiles: 64 rows x 16 uint4 each (4/thread each)
        #pragma unroll
        for (int p = 0; p < 4; ++p) {
            int slot = tid + p * 256;
            int row  = slot >> 4;
            int c4   = (slot & 15) * 4;
            uint4 kv = *reinterpret_cast<const uint4*>(
                &K[base + (size_t)(k0 + row) * DIM + c4]);
            *reinterpret_cast<uint4*>(&Ks[row * QST + c4]) = kv;
            uint4 vv = *reinterpret_cast<const uint4*>(
                &V[base + (size_t)(k0 + row) * DIM + c4]);
            *reinterpret_cast<uint4*>(&Vs[row * VST + c4]) = vv;
        }
        __syncthreads();

        const bool active = (k0 <= q0 + warp * 16 + 15);
        if (active) {
            // ---- S = Q K^T : 16 x 64 per warp ----
            float s[8][4];
            #pragma unroll
            for (int ni = 0; ni < 8; ++ni)
                #pragma unroll
                for (int j = 0; j < 4; ++j) s[ni][j] = 0.0f;

            #pragma unroll
            for (int ks = 0; ks < 8; ++ks) {
                const unsigned* ab = &Qs[(warp * 16) * QST + ks * 8 + t];
                unsigned a0 = ab[r * QST];
                unsigned a1 = ab[(r + 8) * QST];
                unsigned a2 = ab[r * QST + 4];
                unsigned a3 = ab[(r + 8) * QST + 4];
                #pragma unroll
                for (int ni = 0; ni < 8; ++ni) {
                    const unsigned* bb = &Ks[(ni * 8 + r) * QST + ks * 8 + t];
                    mma_tf32(s[ni], a0, a1, a2, a3, bb[0], bb[4]);
                }
            }

            // ---- scale + causal mask ----
            if (k0 + 63 > q0 + warp * 16) {
                const int rg0 = q0 + row_loc;
                #pragma unroll
                for (int ni = 0; ni < 8; ++ni) {
                    int cg = k0 + ni * 8 + 2 * t;
                    s[ni][0] = (cg     <= rg0    ) ? s[ni][0] * ATTN_SCALE : -CUDART_INF_F;
                    s[ni][1] = (cg + 1 <= rg0    ) ? s[ni][1] * ATTN_SCALE : -CUDART_INF_F;
                    s[ni][2] = (cg     <= rg0 + 8) ? s[ni][2] * ATTN_SCALE : -CUDART_INF_F;
                    s[ni][3] = (cg + 1 <= rg0 + 8) ? s[ni][3] * ATTN_SCALE : -CUDART_INF_F;
                }
            } else {
                #pragma unroll
                for (int ni = 0; ni < 8; ++ni)
                    #pragma unroll
                    for (int j = 0; j < 4; ++j) s[ni][j] *= ATTN_SCALE;
            }

            // ---- online softmax ----
            #pragma unroll
            for (int hh = 0; hh < 2; ++hh) {
                float mx = -CUDART_INF_F;
                #pragma unroll
                for (int ni = 0; ni < 8; ++ni)
                    mx = fmaxf(mx, fmaxf(s[ni][hh * 2], s[ni][hh * 2 + 1]));
                mx = fmaxf(mx, __shfl_xor_sync(0xffffffffu, mx, 1, 4));
                mx = fmaxf(mx, __shfl_xor_sync(0xffffffffu, mx, 2, 4));
                float mnew  = fmaxf(m_i[hh], mx);
                float alpha = __expf(m_i[hh] - mnew);
                m_i[hh] = mnew;
                float rs = 0.0f;
                #pragma unroll
                for (int ni = 0; ni < 8; ++ni) {
                    float p0 = __expf(s[ni][hh * 2]     - mnew);
                    float p1 = __expf(s[ni][hh * 2 + 1] - mnew);
                    s[ni][hh * 2]     = p0;
                    s[ni][hh * 2 + 1] = p1;
                    rs += p0 + p1;
                }
                rs += __shfl_xor_sync(0xffffffffu, rs, 1, 4);
                rs += __shfl_xor_sync(0xffffffffu, rs, 2, 4);
                l_i[hh] = l_i[hh] * alpha + rs;
                #pragma unroll
                for (int ni = 0; ni < 8; ++ni) {
                    o[ni][hh * 2]     *= alpha;
                    o[ni][hh * 2 + 1] *= alpha;
                }
            }

            // ---- stage P (A-frag layout, own rows) ----
            #pragma unroll
            for (int ni = 0; ni < 8; ++ni) {
                uint2 p01 = make_uint2(f2tf(s[ni][0]), f2tf(s[ni][1]));
                uint2 p23 = make_uint2(f2tf(s[ni][2]), f2tf(s[ni][3]));
                *reinterpret_cast<uint2*>(&Ps[row_loc * QST + ni * 8 + 2 * t])       = p01;
                *reinterpret_cast<uint2*>(&Ps[(row_loc + 8) * QST + ni * 8 + 2 * t]) = p23;
            }
            __syncwarp();

            // ---- O += P V ----
            #pragma unroll
            for (int ks = 0; ks < 8; ++ks) {
                const unsigned* ab = &Ps[(warp * 16) * QST + ks * 8 + t];
                unsigned a0 = ab[r * QST];
                unsigned a1 = ab[(r + 8) * QST];
                unsigned a2 = ab[r * QST + 4];
                unsigned a3 = ab[(r + 8) * QST + 4];
                #pragma unroll
                for (int ni = 0; ni < 8; ++ni) {
                    unsigned b0 = Vs[(ks * 8 + t) * VST + ni * 8 + r];
                    unsigned b1 = Vs[(ks * 8 + t + 4) * VST + ni * 8 + r];
                    mma_tf32(o[ni], a0, a1, a2, a3, b0, b1);
                }
            }
        }
        __syncthreads();
    }

    // ---- normalize + tf32-rounded store ----
    #pragma unroll
    for (int hh = 0; hh < 2; ++hh) {
        float inv_l = 1.0f / l_i[hh];
        int row = q0 + row_loc + hh * 8;
        #pragma unroll
        for (int ni = 0; ni < 8; ++ni) {
            float v0 = __uint_as_float(f2tf(o[ni][hh * 2]     * inv_l));
            float v1 = __uint_as_float(f2tf(o[ni][hh * 2 + 1] * inv_l));
            *reinterpret_cast<float2*>(
                &O[base + (size_t)row * DIM + ni * 8 + 2 * t]) = make_float2(v0, v1);
        }
    }
}

// ---------------------------------------------------------------------------
// Launch
// ---------------------------------------------------------------------------
extern "C" void kernel_launch(void* const* d_in, const int* in_sizes, int n_in,
                              void* d_out, int out_size)
{
    const float* x  = (const float*)d_in[0];
    const float* Wq = (const float*)d_in[2];
    const float* Wk = (const float*)d_in[3];
    const float* Wv = (const float*)d_in[4];
    const float* Wo = (const float*)d_in[5];
    float* out = (float*)d_out;

    float *QKV, *AOd, *Xt, *Wt;
    cudaGetSymbolAddress((void**)&QKV, g_QKV);
    cudaGetSymbolAddress((void**)&AOd, g_AO);
    cudaGetSymbolAddress((void**)&Xt,  g_Xt);
    cudaGetSymbolAddress((void**)&Wt,  g_Wt);

    const int smem_flash = FL_SMEMW * sizeof(unsigned);   // 105472
    static bool attr_set = false;
    if (!attr_set) {
        cudaFuncSetAttribute(flash_tf32,
                             cudaFuncAttributeMaxDynamicSharedMemorySize, smem_flash);
        cudaFuncSetAttribute(gemm_tc<true>,
                             cudaFuncAttributeMaxDynamicSharedMemorySize, SMEM_GEMM);
        cudaFuncSetAttribute(gemm_tc<false>,
                             cudaFuncAttributeMaxDynamicSharedMemorySize, SMEM_GEMM);
        attr_set = true;
    }

    // pre-round to tf32
    cvt_tf32_k<<<1024, 256>>>((const float4*)x,  (float4*)Xt, MTOT * DIM / 4);
    cvt_tf32_k<<<256, 256>>>((const float4*)Wq, (float4*)(Wt + 0 * DIM * DIM), DIM * DIM / 4);
    cvt_tf32_k<<<256, 256>>>((const float4*)Wk, (float4*)(Wt + 1 * DIM * DIM), DIM * DIM / 4);
    cvt_tf32_k<<<256, 256>>>((const float4*)Wv, (float4*)(Wt + 2 * DIM * DIM), DIM * DIM / 4);
    cvt_tf32_k<<<256, 256>>>((const float4*)Wo, (float4*)(Wt + 3 * DIM * DIM), DIM * DIM / 4);

    // fused Q,K,V projections (grid.z selects weight/output slab)
    dim3 gQKV(DIM / 128, MTOT / 128, 3);   // (8, 64, 3)
    gemm_tc<true><<<gQKV, 256, SMEM_GEMM>>>(Xt, Wt, QKV);

    const float* Qd = QKV;
    const float* Kd = QKV + (size_t)MTOT * DIM;
    const float* Vd = QKV + 2 * (size_t)MTOT * DIM;

    dim3 gF(SEQ / 128, NHEAD, BATCH);      // (16, 16, 4)
    flash_tf32<<<gF, 256, smem_flash>>>(Qd, Kd, Vd, AOd);

    dim3 gO(DIM / 128, MTOT / 128, 1);
    gemm_tc<false><<<gO, 256, SMEM_GEMM>>>(AOd, Wt + 3 * (size_t)DIM * DIM, out);
}